// round 5
// baseline (speedup 1.0000x reference)
#include <cuda_runtime.h>
#include <cuda_bf16.h>
#include <cstdint>

// Problem constants (fixed shapes)
#define DD   256   // feature dim
#define KK   256   // num centers
#define OUTD 128   // output dim

// ---------------- constant precompute scratch (device globals) ----------------
__device__ __align__(16) float          g_s[DD];     // relu(sigma)
__device__ __align__(16) float          g_SV[OUTD];  // sum_k V[k,o]
__device__ __align__(16) float          g_Bp[OUTD];  // relu(W0)+sum relu(Wk) - sum c2*V
// Packed B fragments (bf16): uint4 index = (k16*8 + j)*32 + lane, j covers n-tiles {2j,2j+1}
__device__ __align__(16) __nv_bfloat16  g_Bpk[16 * 8 * 32 * 4 * 2];   // 64KB

// ---------------- packed-B writer ----------------
__device__ __forceinline__ void write_Bpk(int o, int d, float val) {
    int nt = o >> 3, q = o & 7;
    int k16 = d >> 4, r = d & 15;
    int i = r >> 3, l = (r & 7) >> 1, h = r & 1;
    int lane = q * 4 + l;
    int u32idx = ((k16 * 8 + (nt >> 1)) * 32 + lane) * 4 + (nt & 1) * 2 + i;
    g_Bpk[u32idx * 2 + h] = __float2bfloat16(val);
}

// ---------------- fused prep: SV, Bp, packed M2 — 2 output cols per block ------
__global__ void prep_kernel(const float* __restrict__ sigma,
                            const float* __restrict__ center,
                            const float* __restrict__ width,
                            const float* __restrict__ wout) {
    const int o0 = blockIdx.x * 2;
    const int o1 = o0 + 1;
    const int t = threadIdx.x;       // k index for reductions, d index for M2/CV
    __shared__ float V0[KK], V1[KK];
    __shared__ float red[6][8];

    const float s = fmaxf(sigma[t], 0.0f);
    if (blockIdx.x == 0) g_s[t] = s;

    float wk = fmaxf(width[t], 0.0f);
    float w0 = fmaxf(wout[(1 + t) * OUTD + o0], 0.0f);
    float w1 = fmaxf(wout[(1 + t) * OUTD + o1], 0.0f);
    float v0 = wk * w0, v1 = wk * w1;
    V0[t] = v0; V1[t] = v1;

    // SV and SW reductions (k = t)
    float r0 = v0, r1 = w0, r3 = v1, r4 = w1;
    #pragma unroll
    for (int off = 16; off; off >>= 1) {
        r0 += __shfl_xor_sync(0xffffffffu, r0, off);
        r1 += __shfl_xor_sync(0xffffffffu, r1, off);
        r3 += __shfl_xor_sync(0xffffffffu, r3, off);
        r4 += __shfl_xor_sync(0xffffffffu, r4, off);
    }
    const int warp = t >> 5, lane = t & 31;
    if (lane == 0) {
        red[0][warp] = r0; red[1][warp] = r1;
        red[3][warp] = r3; red[4][warp] = r4;
    }
    __syncthreads();   // V0/V1 ready, red[0,1,3,4] ready

    // M2[d=t][o] = 2*sum_k c[k][t]*V[k][o];  CV partial: s_t * sum_k c[k][t]^2 * V[k][o]
    float m0 = 0, m1 = 0, q0 = 0, q1 = 0;
    #pragma unroll 4
    for (int k = 0; k < KK; k++) {
        float c = center[k * DD + t];
        float cs = c * c;
        m0 = fmaf(c, V0[k], m0);
        m1 = fmaf(c, V1[k], m1);
        q0 = fmaf(cs, V0[k], q0);
        q1 = fmaf(cs, V1[k], q1);
    }
    write_Bpk(o0, t, 2.0f * m0);
    write_Bpk(o1, t, 2.0f * m1);

    q0 *= s; q1 *= s;
    #pragma unroll
    for (int off = 16; off; off >>= 1) {
        q0 += __shfl_xor_sync(0xffffffffu, q0, off);
        q1 += __shfl_xor_sync(0xffffffffu, q1, off);
    }
    if (lane == 0) { red[2][warp] = q0; red[5][warp] = q1; }
    __syncthreads();

    if (t < 2) {
        const int o = (t == 0) ? o0 : o1;
        const float* a = red[3 * t];
        const float* b = red[3 * t + 1];
        const float* c = red[3 * t + 2];
        float sv = 0, sw = 0, cv = 0;
        #pragma unroll
        for (int w = 0; w < 8; w++) { sv += a[w]; sw += b[w]; cv += c[w]; }
        g_SV[o] = sv;
        g_Bp[o] = fmaxf(wout[o], 0.0f) + sw - cv;
    }
}

// ---------------- helpers ----------------
__device__ __forceinline__ uint32_t pack_bf16x2(float lo, float hi) {
    uint32_t r;
    asm("cvt.rn.bf16x2.f32 %0, %1, %2;" : "=r"(r) : "f"(hi), "f"(lo));
    return r;
}

__device__ __forceinline__ void mma16816(float* c, uint32_t a0, uint32_t a1,
                                         uint32_t a2, uint32_t a3,
                                         uint32_t b0, uint32_t b1) {
    asm volatile(
        "mma.sync.aligned.m16n8k16.row.col.f32.bf16.bf16.f32 "
        "{%0,%1,%2,%3}, {%4,%5,%6,%7}, {%8,%9}, {%0,%1,%2,%3};"
        : "+f"(c[0]), "+f"(c[1]), "+f"(c[2]), "+f"(c[3])
        : "r"(a0), "r"(a1), "r"(a2), "r"(a3), "r"(b0), "r"(b1));
}

__device__ __forceinline__ void ldsm_x4(uint32_t& r0, uint32_t& r1,
                                        uint32_t& r2, uint32_t& r3, uint32_t addr) {
    asm volatile("ldmatrix.sync.aligned.m8n8.x4.shared.b16 {%0,%1,%2,%3}, [%4];"
        : "=r"(r0), "=r"(r1), "=r"(r2), "=r"(r3) : "r"(addr));
}

__device__ __forceinline__ void cpa16(uint32_t dst, const void* src) {
    asm volatile("cp.async.cg.shared.global [%0], [%1], 16;"
                 :: "r"(dst), "l"(src) : "memory");
}
#define CPA_COMMIT() asm volatile("cp.async.commit_group;" ::: "memory")
#define CPA_WAIT(n)  asm volatile("cp.async.wait_group %0;" :: "n"(n) : "memory")

// ---------------- SMEM layout (dynamic, 1024B-aligned base) ----------------
#define SMEM_RAW    0         // 2 x 32KB raw x fp32 (double buffer); reused as epilogue fbuf
#define SMEM_A      65536     // 16KB bf16 xs tile (R3 swizzle)
#define SMEM_X2     81920     // 128 floats
#define SMEM_BYTES  (82432 + 1024)

// ---------------- main kernel: out = Bp - x2*SV + xs @ M2 ----------------
// 256 threads = 8 warps, 4(m) x 2(n), warp tile 32x64, block tile 128x128.
// cp.async double-buffered raw x; per-thread readback (no sync needed for rawX).
__global__ void __launch_bounds__(256, 2)
rbf_main_kernel(const float* __restrict__ x, float* __restrict__ out) {
    extern __shared__ char smem_raw[];
    const uint32_t sb0 = (uint32_t)__cvta_generic_to_shared(smem_raw);
    const uint32_t sb  = (sb0 + 1023u) & ~1023u;
    char* smem = smem_raw + (sb - sb0);

    const int tid  = threadIdx.x;
    const int warp = tid >> 5;
    const int lane = tid & 31;
    const int warp_m = warp >> 1;     // 0..3
    const int warp_n = warp & 1;      // 0..1
    const int quad  = lane >> 4 ? 0 : 0;  // placeholder (unused)
    const int q8    = lane >> 2;      // 0..7
    const int qlane = lane & 3;       // 0..3

    const int row0 = blockIdx.x * 128;
    const int srow = tid >> 4;        // 0..15
    const int scol = tid & 15;        // 0..15

    float* x2_sh = (float*)(smem + SMEM_X2);

    // ---- cp.async prologue: chunks 0 and 1 ----
    const float* xbase = x + (size_t)(row0 + srow) * DD + scol * 4;
    #pragma unroll
    for (int cc = 0; cc < 2; cc++) {
        const uint32_t db = sb + SMEM_RAW + cc * 32768 + srow * 256 + scol * 16;
        const float* s0 = xbase + cc * 64;
        #pragma unroll
        for (int p = 0; p < 8; p++)
            cpa16(db + p * 4096, s0 + (size_t)p * 16 * DD);
        CPA_COMMIT();
    }

    float acc[2][8][4];
    #pragma unroll
    for (int mt = 0; mt < 2; mt++)
        #pragma unroll
        for (int nt = 0; nt < 8; nt++)
            #pragma unroll
            for (int i = 0; i < 4; i++) acc[mt][nt][i] = 0.0f;

    float x2p[8] = {0, 0, 0, 0, 0, 0, 0, 0};

    const uint4* Bb = reinterpret_cast<const uint4*>(g_Bpk) + warp_n * 128 + lane;
    const uint32_t abase = sb + SMEM_A;
    const int row_l = warp_m * 32 + (lane & 15);
    const uint32_t lds_swz  = (uint32_t)((row_l & 7) << 4);
    const uint32_t lds_koff = (uint32_t)((lane >> 4) << 4);

    #pragma unroll
    for (int c = 0; c < 4; c++) {
        // wait: chunk c's rawX (this thread's bytes) has landed
        if (c < 3) { CPA_WAIT(1); } else { CPA_WAIT(0); }

        const char* rb = smem + SMEM_RAW + (c & 1) * 32768 + srow * 256 + scol * 16;
        const float4 sv4 = *reinterpret_cast<const float4*>(g_s + c * 64 + scol * 4);

        #pragma unroll
        for (int p = 0; p < 8; p++) {
            const int r = p * 16 + srow;
            const float4 v = *reinterpret_cast<const float4*>(rb + p * 4096);
            float a = v.x * sv4.x, b = v.y * sv4.y, cc2 = v.z * sv4.z, d = v.w * sv4.w;
            x2p[p] += a * v.x + b * v.y + cc2 * v.z + d * v.w;
            uint2 packed = make_uint2(pack_bf16x2(a, b), pack_bf16x2(cc2, d));
            const uint32_t off = (uint32_t)(r * 128 + ((scol * 8) ^ ((r & 7) << 4)));
            *reinterpret_cast<uint2*>(smem + SMEM_A + off) = packed;
        }

        // prefetch chunk c+2 into the buffer we just finished reading (own bytes only)
        if (c < 2) {
            const uint32_t db = sb + SMEM_RAW + (c & 1) * 32768 + srow * 256 + scol * 16;
            const float* s0 = xbase + (c + 2) * 64;
            #pragma unroll
            for (int p = 0; p < 8; p++)
                cpa16(db + p * 4096, s0 + (size_t)p * 16 * DD);
            CPA_COMMIT();
        }

        __syncthreads();   // A tile ready

        #pragma unroll
        for (int q = 0; q < 4; q++) {
            const int k16 = c * 4 + q;
            uint4 b4[4];
            #pragma unroll
            for (int jj = 0; jj < 4; jj++)
                b4[jj] = Bb[k16 * 256 + jj * 32];

            #pragma unroll
            for (int mt = 0; mt < 2; mt++) {
                const uint32_t addr = abase + (uint32_t)((row_l + mt * 16) * 128)
                                    + (((uint32_t)(q * 32) + lds_koff) ^ lds_swz);
                uint32_t a0, a1, a2, a3;
                ldsm_x4(a0, a1, a2, a3, addr);
                #pragma unroll
                for (int jj = 0; jj < 4; jj++) {
                    mma16816(acc[mt][2 * jj],     a0, a1, a2, a3, b4[jj].x, b4[jj].y);
                    mma16816(acc[mt][2 * jj + 1], a0, a1, a2, a3, b4[jj].z, b4[jj].w);
                }
            }
        }
        __syncthreads();   // A consumed before next chunk's STS
    }

    // ---- finalize x2 (reduce over the 16 lanes sharing a row) ----
    #pragma unroll
    for (int p = 0; p < 8; p++) {
        float v = x2p[p];
        v += __shfl_xor_sync(0xffffffffu, v, 1);
        v += __shfl_xor_sync(0xffffffffu, v, 2);
        v += __shfl_xor_sync(0xffffffffu, v, 4);
        v += __shfl_xor_sync(0xffffffffu, v, 8);
        if (scol == 0) x2_sh[p * 16 + srow] = v;
    }

    // ---- epilogue: restage fragments -> coalesced streaming stores ----
    float* fb = (float*)(smem + SMEM_RAW);    // 128 rows x 34 floats (padded)
    const int rr = tid >> 3, f4 = tid & 7;

    #pragma unroll 1
    for (int cc = 0; cc < 4; cc++) {
        if (warp_n == (cc >> 1)) {
            #pragma unroll
            for (int ntl = 0; ntl < 4; ntl++) {
                const int nt = (cc & 1) * 4 + ntl;
                const int lcol = ntl * 8 + 2 * qlane;
                #pragma unroll
                for (int mt = 0; mt < 2; mt++) {
                    const int r0 = warp_m * 32 + mt * 16 + q8;
                    *reinterpret_cast<float2*>(fb + r0 * 34 + lcol) =
                        make_float2(acc[mt][nt][0], acc[mt][nt][1]);
                    *reinterpret_cast<float2*>(fb + (r0 + 8) * 34 + lcol) =
                        make_float2(acc[mt][nt][2], acc[mt][nt][3]);
                }
            }
        }
        __syncthreads();

        const int col0 = cc * 32 + f4 * 4;
        const float4 bp  = *reinterpret_cast<const float4*>(g_Bp + col0);
        const float4 svv = *reinterpret_cast<const float4*>(g_SV + col0);
        #pragma unroll
        for (int p = 0; p < 4; p++) {
            const int row = rr + p * 32;
            const float* ob = fb + row * 34 + f4 * 4;
            float2 u0 = *reinterpret_cast<const float2*>(ob);
            float2 u1 = *reinterpret_cast<const float2*>(ob + 2);
            const float x2v = x2_sh[row];
            float4 o;
            o.x = u0.x + bp.x - x2v * svv.x;
            o.y = u0.y + bp.y - x2v * svv.y;
            o.z = u1.x + bp.z - x2v * svv.z;
            o.w = u1.y + bp.w - x2v * svv.w;
            __stcs(reinterpret_cast<float4*>(out + (size_t)(row0 + row) * OUTD + col0), o);
        }
        __syncthreads();
    }
}

// ---------------- launcher ----------------
extern "C" void kernel_launch(void* const* d_in, const int* in_sizes, int n_in,
                              void* d_out, int out_size) {
    const float* x      = (const float*)d_in[0];  // [N, D]
    const float* center = (const float*)d_in[1];  // [K, D]
    const float* sigma  = (const float*)d_in[2];  // [D]
    const float* width  = (const float*)d_in[3];  // [K]
    const float* wout   = (const float*)d_in[4];  // [1+K, OUT]
    float* out = (float*)d_out;

    const int N = in_sizes[0] / DD;

    cudaFuncSetAttribute(rbf_main_kernel,
                         cudaFuncAttributeMaxDynamicSharedMemorySize, SMEM_BYTES);

    prep_kernel<<<OUTD / 2, 256>>>(sigma, center, width, wout);
    rbf_main_kernel<<<N / 128, 256, SMEM_BYTES>>>(x, out);
}

// round 6
// speedup vs baseline: 1.3054x; 1.3054x over previous
#include <cuda_runtime.h>
#include <cuda_bf16.h>
#include <cstdint>

// Problem constants (fixed shapes)
#define DD   256   // feature dim
#define KK   256   // num centers
#define OUTD 128   // output dim

// ---------------- constant precompute scratch (device globals) ----------------
__device__ __align__(16) float          g_s[DD];     // relu(sigma)
__device__ __align__(16) float          g_SV[OUTD];  // sum_k V[k,o]
__device__ __align__(16) float          g_Bp[OUTD];  // relu(W0)+sum relu(Wk) - sum c2*V
// Packed B fragments (bf16): uint4 index = (k16*8 + j)*32 + lane, j covers n-tiles {2j,2j+1}
__device__ __align__(16) __nv_bfloat16  g_Bpk[16 * 8 * 32 * 4 * 2];   // 64KB

// ---------------- packed-B writer ----------------
__device__ __forceinline__ void write_Bpk(int o, int d, float val) {
    int nt = o >> 3, q = o & 7;
    int k16 = d >> 4, r = d & 15;
    int i = r >> 3, l = (r & 7) >> 1, h = r & 1;
    int lane = q * 4 + l;
    int u32idx = ((k16 * 8 + (nt >> 1)) * 32 + lane) * 4 + (nt & 1) * 2 + i;
    g_Bpk[u32idx * 2 + h] = __float2bfloat16(val);
}

// ---------------- fused prep: SV, Bp, packed M2 — 2 output cols per block ------
__global__ void prep_kernel(const float* __restrict__ sigma,
                            const float* __restrict__ center,
                            const float* __restrict__ width,
                            const float* __restrict__ wout) {
    const int o0 = blockIdx.x * 2;
    const int o1 = o0 + 1;
    const int t = threadIdx.x;       // k index for reductions, d index for M2/CV
    __shared__ float V0[KK], V1[KK];
    __shared__ float red[6][8];

    const float s = fmaxf(sigma[t], 0.0f);
    if (blockIdx.x == 0) g_s[t] = s;

    float wk = fmaxf(width[t], 0.0f);
    float w0 = fmaxf(wout[(1 + t) * OUTD + o0], 0.0f);
    float w1 = fmaxf(wout[(1 + t) * OUTD + o1], 0.0f);
    float v0 = wk * w0, v1 = wk * w1;
    V0[t] = v0; V1[t] = v1;

    float r0 = v0, r1 = w0, r3 = v1, r4 = w1;
    #pragma unroll
    for (int off = 16; off; off >>= 1) {
        r0 += __shfl_xor_sync(0xffffffffu, r0, off);
        r1 += __shfl_xor_sync(0xffffffffu, r1, off);
        r3 += __shfl_xor_sync(0xffffffffu, r3, off);
        r4 += __shfl_xor_sync(0xffffffffu, r4, off);
    }
    const int warp = t >> 5, lane = t & 31;
    if (lane == 0) {
        red[0][warp] = r0; red[1][warp] = r1;
        red[3][warp] = r3; red[4][warp] = r4;
    }
    __syncthreads();   // V0/V1 ready

    // M2[d=t][o] = 2*sum_k c[k][t]*V[k][o];  CV partial: s_t * sum_k c[k][t]^2 * V[k][o]
    float m0 = 0, m1 = 0, q0 = 0, q1 = 0;
    #pragma unroll 4
    for (int k = 0; k < KK; k++) {
        float c = center[k * DD + t];
        float cs = c * c;
        m0 = fmaf(c, V0[k], m0);
        m1 = fmaf(c, V1[k], m1);
        q0 = fmaf(cs, V0[k], q0);
        q1 = fmaf(cs, V1[k], q1);
    }
    write_Bpk(o0, t, 2.0f * m0);
    write_Bpk(o1, t, 2.0f * m1);

    q0 *= s; q1 *= s;
    #pragma unroll
    for (int off = 16; off; off >>= 1) {
        q0 += __shfl_xor_sync(0xffffffffu, q0, off);
        q1 += __shfl_xor_sync(0xffffffffu, q1, off);
    }
    if (lane == 0) { red[2][warp] = q0; red[5][warp] = q1; }
    __syncthreads();

    if (t < 2) {
        const int o = (t == 0) ? o0 : o1;
        const float* a = red[3 * t];
        const float* b = red[3 * t + 1];
        const float* c = red[3 * t + 2];
        float sv = 0, sw = 0, cv = 0;
        #pragma unroll
        for (int w = 0; w < 8; w++) { sv += a[w]; sw += b[w]; cv += c[w]; }
        g_SV[o] = sv;
        g_Bp[o] = fmaxf(wout[o], 0.0f) + sw - cv;
    }
}

// ---------------- helpers ----------------
__device__ __forceinline__ uint32_t pack_bf16x2(float lo, float hi) {
    uint32_t r;
    asm("cvt.rn.bf16x2.f32 %0, %1, %2;" : "=r"(r) : "f"(hi), "f"(lo));
    return r;
}

__device__ __forceinline__ void mma16816(float* c, uint32_t a0, uint32_t a1,
                                         uint32_t a2, uint32_t a3,
                                         uint32_t b0, uint32_t b1) {
    asm volatile(
        "mma.sync.aligned.m16n8k16.row.col.f32.bf16.bf16.f32 "
        "{%0,%1,%2,%3}, {%4,%5,%6,%7}, {%8,%9}, {%0,%1,%2,%3};"
        : "+f"(c[0]), "+f"(c[1]), "+f"(c[2]), "+f"(c[3])
        : "r"(a0), "r"(a1), "r"(a2), "r"(a3), "r"(b0), "r"(b1));
}

__device__ __forceinline__ void ldsm_x4(uint32_t& r0, uint32_t& r1,
                                        uint32_t& r2, uint32_t& r3, uint32_t addr) {
    asm volatile("ldmatrix.sync.aligned.m8n8.x4.shared.b16 {%0,%1,%2,%3}, [%4];"
        : "=r"(r0), "=r"(r1), "=r"(r2), "=r"(r3) : "r"(addr));
}

// ---------------- main kernel: out = Bp - x2*SV + xs @ M2 ----------------
// 128 threads = 4 warps, warp grid 2(m) x 2(n), warp tile 32x64.
// Block tile 64 rows x 128 cols. Double-buffered A tile, 1 sync per chunk.
// 4 blocks/SM for latency hiding across independent pipelines.
__global__ void __launch_bounds__(128, 4)
rbf_main_kernel(const float* __restrict__ x, float* __restrict__ out) {
    __shared__ __align__(16) char smA[2][8192];   // bf16 A tiles, SW swizzled
    __shared__ float x2_sh[64];

    const int tid  = threadIdx.x;
    const int warp = tid >> 5;
    const int lane = tid & 31;
    const int warp_m = warp >> 1;     // 0..1
    const int warp_n = warp & 1;      // 0..1
    const int q8    = lane >> 2;      // 0..7
    const int qlane = lane & 3;       // 0..3

    const int row0 = blockIdx.x * 64;
    const int srow = tid >> 4;        // 0..7
    const int scol = tid & 15;        // 0..15

    const uint32_t abase = (uint32_t)__cvta_generic_to_shared(smA);
    const uint4* Bb = reinterpret_cast<const uint4*>(g_Bpk) + warp_n * 128 + lane;
    const int row_l = warp_m * 32 + (lane & 15);
    const uint32_t lds_swz  = (uint32_t)((row_l & 7) << 4);
    const uint32_t lds_koff = (uint32_t)((lane >> 4) << 4);
    const uint32_t sts_base = abase + (uint32_t)(((scol * 8) ^ ((srow & 7) << 4)) + srow * 128);

    float acc[2][8][4];
    #pragma unroll
    for (int mt = 0; mt < 2; mt++)
        #pragma unroll
        for (int nt = 0; nt < 8; nt++)
            #pragma unroll
            for (int i = 0; i < 4; i++) acc[mt][nt][i] = 0.0f;

    float x2p[8] = {0, 0, 0, 0, 0, 0, 0, 0};

    // prologue: load chunk 0 (rows p*8+srow, 16B each, fully coalesced)
    const float* xbase = x + (size_t)(row0 + srow) * DD + scol * 4;
    float4 v[8];
    #pragma unroll
    for (int p = 0; p < 8; p++)
        v[p] = __ldcs(reinterpret_cast<const float4*>(xbase + (size_t)p * 8 * DD));

    #pragma unroll
    for (int c = 0; c < 4; c++) {
        const float4 sv4 = *reinterpret_cast<const float4*>(g_s + c * 64 + scol * 4);
        const uint32_t ab = sts_base + (uint32_t)((c & 1) * 8192);

        // convert + STS + x2 accumulate (consumes v[])
        #pragma unroll
        for (int p = 0; p < 8; p++) {
            const float4 w = v[p];
            float a = w.x * sv4.x, b = w.y * sv4.y, cc2 = w.z * sv4.z, d = w.w * sv4.w;
            x2p[p] += a * w.x + b * w.y + cc2 * w.z + d * w.w;
            uint2 packed = make_uint2(pack_bf16x2(a, b), pack_bf16x2(cc2, d));
            asm volatile("st.shared.v2.b32 [%0], {%1, %2};"
                         :: "r"(ab + (uint32_t)(p * 1024)), "r"(packed.x), "r"(packed.y)
                         : "memory");
        }

        // issue next chunk's loads (overlap with this chunk's MMA)
        if (c < 3) {
            const float* nb = xbase + (c + 1) * 64;
            #pragma unroll
            for (int p = 0; p < 8; p++)
                v[p] = __ldcs(reinterpret_cast<const float4*>(nb + (size_t)p * 8 * DD));
        }

        __syncthreads();   // A[c&1] ready (also: all MMAs on A[(c-1)&1] finished)

        const uint32_t lb = abase + (uint32_t)((c & 1) * 8192);
        #pragma unroll
        for (int q = 0; q < 4; q++) {
            const int k16 = c * 4 + q;
            uint4 b4[4];
            #pragma unroll
            for (int jj = 0; jj < 4; jj++)
                b4[jj] = Bb[k16 * 256 + jj * 32];

            #pragma unroll
            for (int mt = 0; mt < 2; mt++) {
                const uint32_t addr = lb + (uint32_t)((row_l + mt * 16) * 128)
                                    + (((uint32_t)(q * 32) + lds_koff) ^ lds_swz);
                uint32_t a0, a1, a2, a3;
                ldsm_x4(a0, a1, a2, a3, addr);
                #pragma unroll
                for (int jj = 0; jj < 4; jj++) {
                    mma16816(acc[mt][2 * jj],     a0, a1, a2, a3, b4[jj].x, b4[jj].y);
                    mma16816(acc[mt][2 * jj + 1], a0, a1, a2, a3, b4[jj].z, b4[jj].w);
                }
            }
        }
        // no trailing sync: next iteration's STS targets the other buffer,
        // and the next __syncthreads orders MMA(c) before STS(c+2).
    }

    // ---- finalize x2 (reduce over the 16 lanes sharing a row) ----
    #pragma unroll
    for (int p = 0; p < 8; p++) {
        float w = x2p[p];
        w += __shfl_xor_sync(0xffffffffu, w, 1);
        w += __shfl_xor_sync(0xffffffffu, w, 2);
        w += __shfl_xor_sync(0xffffffffu, w, 4);
        w += __shfl_xor_sync(0xffffffffu, w, 8);
        if (scol == 0) x2_sh[p * 8 + srow] = w;
    }
    __syncthreads();   // x2 ready; all MMAs done -> smA reusable as fbuf

    // ---- epilogue: restage fragments -> coalesced streaming stores ----
    float* fb = reinterpret_cast<float*>(smA);   // 64 rows x 34 floats (8.5KB)
    const int rr = tid >> 3, f4 = tid & 7;

    #pragma unroll 1
    for (int cc = 0; cc < 4; cc++) {
        if (warp_n == (cc >> 1)) {
            #pragma unroll
            for (int ntl = 0; ntl < 4; ntl++) {
                const int nt = (cc & 1) * 4 + ntl;
                const int lcol = ntl * 8 + 2 * qlane;
                #pragma unroll
                for (int mt = 0; mt < 2; mt++) {
                    const int r0 = warp_m * 32 + mt * 16 + q8;
                    *reinterpret_cast<float2*>(fb + r0 * 34 + lcol) =
                        make_float2(acc[mt][nt][0], acc[mt][nt][1]);
                    *reinterpret_cast<float2*>(fb + (r0 + 8) * 34 + lcol) =
                        make_float2(acc[mt][nt][2], acc[mt][nt][3]);
                }
            }
        }
        __syncthreads();

        const int col0 = cc * 32 + f4 * 4;
        const float4 bp  = *reinterpret_cast<const float4*>(g_Bp + col0);
        const float4 svv = *reinterpret_cast<const float4*>(g_SV + col0);
        #pragma unroll
        for (int p = 0; p < 4; p++) {
            const int row = rr + p * 16;
            const float* ob = fb + row * 34 + f4 * 4;
            float2 u0 = *reinterpret_cast<const float2*>(ob);
            float2 u1 = *reinterpret_cast<const float2*>(ob + 2);
            const float x2v = x2_sh[row];
            float4 o;
            o.x = u0.x + bp.x - x2v * svv.x;
            o.y = u0.y + bp.y - x2v * svv.y;
            o.z = u1.x + bp.z - x2v * svv.z;
            o.w = u1.y + bp.w - x2v * svv.w;
            __stcs(reinterpret_cast<float4*>(out + (size_t)(row0 + row) * OUTD + col0), o);
        }
        __syncthreads();
    }
}

// ---------------- launcher ----------------
extern "C" void kernel_launch(void* const* d_in, const int* in_sizes, int n_in,
                              void* d_out, int out_size) {
    const float* x      = (const float*)d_in[0];  // [N, D]
    const float* center = (const float*)d_in[1];  // [K, D]
    const float* sigma  = (const float*)d_in[2];  // [D]
    const float* width  = (const float*)d_in[3];  // [K]
    const float* wout   = (const float*)d_in[4];  // [1+K, OUT]
    float* out = (float*)d_out;

    const int N = in_sizes[0] / DD;

    prep_kernel<<<OUTD / 2, 256>>>(sigma, center, width, wout);
    rbf_main_kernel<<<N / 64, 128>>>(x, out);
}